// round 15
// baseline (speedup 1.0000x reference)
#include <cuda_runtime.h>
#include <cstdint>

#define NV   32768
#define KC   8192
#define DIMV 64
#define ND   (NV * DIMV)

// ---- main geometry ----
#define ROWS  32
#define NBLK  (NV / ROWS)            // 1024
#define CCH   512                    // codes per chunk
#define NCH   (KC / CCH)             // 16

// main smem (bytes)
#define SM_Z    0                    // 32 rows * 17 words * 4 = 2176
#define SM_E    2176                 // 2 bufs * 512*16*4 = 65536
#define SM_ESQ  (SM_E + 65536)       // 2 * 2048
#define SM_RED  (SM_ESQ + 4096)      // rb 1024 + rb2 1024 + ri 1024
#define SM_SUMZ (SM_RED + 3072)      // 32 floats
#define SMEM_MAIN (SM_SUMZ + 128)    // 75136

// ---- fixup geometry (proven in R14) ----
#define FROWS   16
#define FCCH    256
#define FNCH    (KC / FCCH)          // 32
#define FSTR    272
#define FEBUF   (FCCH * FSTR)        // 69632
#define FSM_Z   0
#define FSM_E   4352
#define FSM_RED 143616
#define SMEM_FIX 144640

__device__ __align__(256) int g_qcb[KC * 16];   // packed s8x4, 16 words/code
__device__ float g_esq[KC];                     // 0.5*||e||^2 exact fp32
__device__ float g_block_sums[NBLK];
__device__ unsigned g_amz_bits, g_ame_bits, g_maxsume_bits;  // |max| as float bits
__device__ int   g_fix_count;
__device__ int   g_fix_list[NV];
__device__ float g_loss_corr;

__device__ __forceinline__ void cp16(void* dst_s, const void* src_g) {
    uint32_t d = (uint32_t)__cvta_generic_to_shared(dst_s);
    asm volatile("cp.async.cg.shared.global [%0], [%1], 16;" :: "r"(d), "l"(src_g));
}
#define CP_COMMIT() asm volatile("cp.async.commit_group;" ::: "memory")
#define CP_WAIT1()  asm volatile("cp.async.wait_group 1;" ::: "memory")
#define CP_WAIT0()  asm volatile("cp.async.wait_group 0;" ::: "memory")

__device__ __forceinline__ void ffma2(unsigned long long &d,
                                      unsigned long long a,
                                      unsigned long long b) {
    asm("fma.rn.f32x2 %0, %1, %2, %0;" : "+l"(d) : "l"(a), "l"(b));
}

__device__ __forceinline__ int q8(float v, float inv_s) {
    float q = fminf(fmaxf(v * inv_s, -127.f), 127.f);
    return __float2int_rn(q);
}

// ---------------- K0: absmax scan + resets ----------------
__global__ void vq_scan(const float* __restrict__ z, const float* __restrict__ cb) {
    int tid = blockIdx.x * blockDim.x + threadIdx.x;
    if (tid == 0) { g_fix_count = 0; g_loss_corr = 0.f; }
    float mz = 0.f, me = 0.f;
    const float4* z4 = reinterpret_cast<const float4*>(z);
    const float4* c4 = reinterpret_cast<const float4*>(cb);
    for (int i = tid; i < ND / 4; i += 65536) {
        float4 v = z4[i];
        mz = fmaxf(mz, fmaxf(fmaxf(fabsf(v.x), fabsf(v.y)), fmaxf(fabsf(v.z), fabsf(v.w))));
    }
    for (int i = tid; i < KC * DIMV / 4; i += 65536) {
        float4 v = c4[i];
        me = fmaxf(me, fmaxf(fmaxf(fabsf(v.x), fabsf(v.y)), fmaxf(fabsf(v.z), fabsf(v.w))));
    }
    #pragma unroll
    for (int off = 16; off >= 1; off >>= 1) {
        mz = fmaxf(mz, __shfl_xor_sync(0xffffffffu, mz, off));
        me = fmaxf(me, __shfl_xor_sync(0xffffffffu, me, off));
    }
    if ((threadIdx.x & 31) == 0) {
        atomicMax(&g_amz_bits, __float_as_uint(mz));
        atomicMax(&g_ame_bits, __float_as_uint(me));
    }
}

// ---------------- K1: quantize codebook + esq + maxsum ----------------
__global__ void vq_qcb(const float* __restrict__ cb) {
    int k = blockIdx.x * blockDim.x + threadIdx.x;
    if (k >= KC) return;
    float se = __uint_as_float(g_ame_bits) / 127.f;
    float inv = 1.f / se;
    float ssq = 0.f, sab = 0.f;
    const float4* row = reinterpret_cast<const float4*>(cb + (size_t)k * DIMV);
    #pragma unroll
    for (int w = 0; w < 16; w++) {
        float4 v = row[w];
        ssq += v.x * v.x + v.y * v.y + v.z * v.z + v.w * v.w;
        sab += fabsf(v.x) + fabsf(v.y) + fabsf(v.z) + fabsf(v.w);
        int q0 = q8(v.x, inv), q1 = q8(v.y, inv), q2 = q8(v.z, inv), q3 = q8(v.w, inv);
        g_qcb[k * 16 + w] = (q0 & 255) | ((q1 & 255) << 8) | ((q2 & 255) << 16) | ((q3 & 255) << 24);
    }
    g_esq[k] = 0.5f * ssq;
    float wm = sab;
    #pragma unroll
    for (int off = 16; off >= 1; off >>= 1)
        wm = fmaxf(wm, __shfl_xor_sync(0xffffffffu, wm, off));
    if ((threadIdx.x & 31) == 0) atomicMax(&g_maxsume_bits, __float_as_uint(wm));
}

// ---------------- K2: dp4a distance + argmin/margin + gather ----------------
__device__ __forceinline__ void cp_chunk(char* smem, int chunk, int buf, int tid) {
    const int* src = g_qcb + (size_t)chunk * CCH * 16;
    char* dbase = smem + SM_E + buf * 32768;
    #pragma unroll
    for (int n = 0; n < 8; n++) {
        int q = tid + 256 * n;              // 0..2047 16B quads
        int code = q >> 2, g4 = q & 3;
        int word = code * 16 + ((g4 * 4) ^ ((((unsigned)code >> 1) & 3) << 2));
        cp16(dbase + word * 4, src + code * 16 + g4 * 4);
    }
    if (tid < 128)
        cp16(smem + SM_ESQ + buf * 2048 + tid * 16, g_esq + chunk * CCH + tid * 4);
}

__global__ __launch_bounds__(256, 2) void vq_main(
    const float* __restrict__ z, const float* __restrict__ cb,
    float* __restrict__ out, int out_size)
{
    extern __shared__ char smem[];
    int* smi = reinterpret_cast<int*>(smem);
    const int tid  = threadIdx.x, lane = tid & 31, wid = tid >> 5;
    const int row_t = lane & 3;             // 4 row-threads/warp
    const int csub  = lane >> 2;            // 8 col-subthreads/warp
    const int ct    = wid * 8 + csub;       // 0..63
    const int xorv  = (((unsigned)ct >> 1) & 3) << 2;
    const int row0  = blockIdx.x * ROWS;

    const float sz = __uint_as_float(g_amz_bits) / 127.f;
    const float se = __uint_as_float(g_ame_bits) / 127.f;
    const float inv_sz = 1.f / sz;
    const float negS = -(sz * se);

    // z tile: quantize fp32 -> s8x4, pad-17 layout; per-row sum|z| for bound
    float* sumz = reinterpret_cast<float*>(smem + SM_SUMZ);
    #pragma unroll
    for (int w = tid; w < 512; w += 256) {
        int r = w >> 4, d4 = w & 15;
        float4 v = reinterpret_cast<const float4*>(z + (size_t)(row0 + r) * DIMV)[d4];
        int q0 = q8(v.x, inv_sz), q1 = q8(v.y, inv_sz), q2 = q8(v.z, inv_sz), q3 = q8(v.w, inv_sz);
        smi[SM_Z / 4 + r * 17 + d4] =
            (q0 & 255) | ((q1 & 255) << 8) | ((q2 & 255) << 16) | ((q3 & 255) << 24);
        float p = fabsf(v.x) + fabsf(v.y) + fabsf(v.z) + fabsf(v.w);
        #pragma unroll
        for (int off = 8; off >= 1; off >>= 1)
            p += __shfl_down_sync(0xffffffffu, p, off);
        if ((lane & 15) == 0) sumz[r] = p;
    }

    cp_chunk(smem, 0, 0, tid);
    CP_COMMIT();

    float best[8], best2[8];
    int   bidx[8];
    #pragma unroll
    for (int k = 0; k < 8; k++) { best[k] = 3.4e38f; best2[k] = 3.4e38f; bidx[k] = 0; }

    for (int c = 0; c < NCH; c++) {
        const int b = c & 1;
        if (c + 1 < NCH) { cp_chunk(smem, c + 1, (c + 1) & 1, tid); CP_COMMIT(); CP_WAIT1(); }
        else             { CP_WAIT0(); }
        __syncthreads();

        const int* Eb = smi + (SM_E + b * 32768) / 4;
        const float* esq_s = reinterpret_cast<const float*>(smem + SM_ESQ + b * 2048);

        int acc[8][8];
        #pragma unroll
        for (int k = 0; k < 8; k++)
            #pragma unroll
            for (int j = 0; j < 8; j++) acc[k][j] = 0;

        #pragma unroll 4
        for (int d = 0; d < 16; d++) {      // 4 dims per word
            int zf[8], ef[8];
            #pragma unroll
            for (int k = 0; k < 8; k++)
                zf[k] = smi[SM_Z / 4 + (row_t + 4 * k) * 17 + d];
            #pragma unroll
            for (int j = 0; j < 8; j++)
                ef[j] = Eb[(ct + 64 * j) * 16 + (d ^ xorv)];
            #pragma unroll
            for (int k = 0; k < 8; k++)
                #pragma unroll
                for (int j = 0; j < 8; j++)
                    acc[k][j] = __dp4a(zf[k], ef[j], acc[k][j]);
        }

        // scores: exact int dot -> float (magic), s = esq - S*dot
        #pragma unroll
        for (int j = 0; j < 8; j++) {
            int code = c * CCH + ct + 64 * j;
            float es = esq_s[ct + 64 * j];
            #pragma unroll
            for (int k = 0; k < 8; k++) {
                float f = __int_as_float(acc[k][j] + 0x4B400000) - 12582912.0f;
                float s = fmaf(negS, f, es);
                if (s < best[k]) { best2[k] = best[k]; best[k] = s; bidx[k] = code; }
                else if (s < best2[k]) best2[k] = s;
            }
        }
        __syncthreads();
    }

    // warp reduce over csub (xor 4,8,16 keep row_t)
    #pragma unroll
    for (int k = 0; k < 8; k++) {
        float b1 = best[k], b2 = best2[k];
        int   i1 = bidx[k];
        #pragma unroll
        for (int off = 4; off <= 16; off <<= 1) {
            float ob  = __shfl_xor_sync(0xffffffffu, b1, off);
            float ob2 = __shfl_xor_sync(0xffffffffu, b2, off);
            int   oi  = __shfl_xor_sync(0xffffffffu, i1, off);
            if (ob < b1 || (ob == b1 && oi < i1)) { b2 = fminf(b1, ob2); b1 = ob; i1 = oi; }
            else                                  { b2 = fminf(ob, b2); }
        }
        best[k] = b1; best2[k] = b2; bidx[k] = i1;
    }
    float* rb  = reinterpret_cast<float*>(smem + SM_RED);
    float* rb2 = rb + 256;
    int*   ri  = reinterpret_cast<int*>(rb + 512);
    if (csub == 0) {
        #pragma unroll
        for (int k = 0; k < 8; k++) {
            int r = row_t + 4 * k;
            rb [wid * 32 + r] = best[k];
            rb2[wid * 32 + r] = best2[k];
            ri [wid * 32 + r] = bidx[k];
        }
    }
    __syncthreads();

    if (tid < ROWS) {
        const int r = tid;
        float b1 = 3.4e38f, b2 = 3.4e38f; int i1 = 0;
        #pragma unroll
        for (int w = 0; w < 8; w++) {
            float ob = rb[w * 32 + r], ob2 = rb2[w * 32 + r];
            int   oi = ri[w * 32 + r];
            if (ob < b1 || (ob == b1 && oi < i1)) { b2 = fminf(b1, ob2); b1 = ob; i1 = oi; }
            else                                  { b2 = fminf(ob, b2); }
        }
        const int grow = row0 + r;
        // worst-case score-error bound from the data itself
        float msume = __uint_as_float(g_maxsume_bits);
        float B = 0.5f * se * sumz[r] + 0.5f * sz * msume + 16.f * sz * se;
        if (b2 - b1 < 2.f * B + 1e-2f) {
            int pos = atomicAdd(&g_fix_count, 1);
            g_fix_list[pos] = grow;
        }
        float lsum = 0.f;
        const float4* crow = reinterpret_cast<const float4*>(cb + (size_t)i1 * DIMV);
        const float4* zrow = reinterpret_cast<const float4*>(z + (size_t)grow * DIMV);
        float4* qrow = reinterpret_cast<float4*>(out + (size_t)grow * DIMV);
        #pragma unroll
        for (int j = 0; j < 16; j++) {
            float4 e = crow[j], zz = zrow[j];
            qrow[j] = e;
            float dx = zz.x - e.x, dy = zz.y - e.y;
            float dz = zz.z - e.z, dw = zz.w - e.w;
            lsum += dx * dx + dy * dy + dz * dz + dw * dw;
        }
        if (out_size >= ND + 2 + NV) out[ND + 2 + grow] = (float)i1;

        #pragma unroll
        for (int off = 16; off >= 1; off >>= 1)
            lsum += __shfl_xor_sync(0xffffffffu, lsum, off);
        if (r == 0) g_block_sums[blockIdx.x] = lsum;
    }
}

// ---------------- K3: exact fp32 rescan of flagged rows (proven R14) ----------------
__global__ __launch_bounds__(256, 1) void vq_fixup(
    const float* __restrict__ z, const float* __restrict__ cb,
    float* __restrict__ out, int out_size)
{
    extern __shared__ char fsm[];
    if (out_size < ND + 2 + NV) return;
    const int tid = threadIdx.x, lane = tid & 31, wid = tid >> 5;
    const int row_t = lane & 3, csub = lane >> 2;
    const int ct = wid * 8 + csub;
    int nfix = g_fix_count; if (nfix > NV) nfix = NV;

    float* z_s = reinterpret_cast<float*>(fsm + FSM_Z);
    float* rbf = reinterpret_cast<float*>(fsm + FSM_RED);
    int*   rif = reinterpret_cast<int*>(rbf + 128);

    for (int g = blockIdx.x; g * FROWS < nfix; g += gridDim.x) {
        const int base = g * FROWS;
        const int cnt  = min(FROWS, nfix - base);
        __syncthreads();

        for (int i = tid; i < FROWS * 16; i += 256) {
            int r = i >> 4, qd = i & 15;
            int zr = g_fix_list[base + min(r, cnt - 1)];
            float4 v = reinterpret_cast<const float4*>(z + (size_t)zr * DIMV)[qd];
            *reinterpret_cast<float4*>(z_s + r * 68 + qd * 4) = v;
        }
        #pragma unroll
        for (int n = 0; n < 16; n++) {
            int q = tid + 256 * n;
            int code = q >> 4, dd = q & 15;
            cp16(fsm + FSM_E + code * FSTR + dd * 16, cb + (size_t)code * DIMV + dd * 4);
        }
        CP_COMMIT();

        float best[4];
        int   bidx[4];
        #pragma unroll
        for (int k = 0; k < 4; k++) { best[k] = 3.4e38f; bidx[k] = 0; }

        for (int c = 0; c < FNCH; c++) {
            const int b = c & 1;
            if (c + 1 < FNCH) {
                const float* src = cb + (size_t)(c + 1) * FCCH * DIMV;
                char* d = fsm + FSM_E + ((c + 1) & 1) * FEBUF;
                #pragma unroll
                for (int n = 0; n < 16; n++) {
                    int q = tid + 256 * n;
                    int code = q >> 4, dd = q & 15;
                    cp16(d + code * FSTR + dd * 16, src + (size_t)code * DIMV + dd * 4);
                }
                CP_COMMIT(); CP_WAIT1();
            } else CP_WAIT0();
            __syncthreads();

            const char* Eb = fsm + FSM_E + b * FEBUF;
            unsigned long long acc[4][4];
            #pragma unroll
            for (int k = 0; k < 4; k++)
                #pragma unroll
                for (int j = 0; j < 4; j++) acc[k][j] = 0ull;

            #pragma unroll 8
            for (int d2 = 0; d2 < 32; d2++) {
                unsigned long long zf[4], ef[4];
                #pragma unroll
                for (int k = 0; k < 4; k++)
                    zf[k] = *reinterpret_cast<const unsigned long long*>(
                        z_s + (row_t + 4 * k) * 68 + d2 * 2);
                #pragma unroll
                for (int j = 0; j < 4; j++)
                    ef[j] = *reinterpret_cast<const unsigned long long*>(
                        Eb + (ct + 64 * j) * FSTR + d2 * 8);
                #pragma unroll
                for (int k = 0; k < 4; k++)
                    #pragma unroll
                    for (int j = 0; j < 4; j++) ffma2(acc[k][j], zf[k], ef[j]);
            }

            #pragma unroll
            for (int j = 0; j < 4; j++) {
                int code = c * FCCH + ct + 64 * j;
                float es = __ldg(&g_esq[code]);
                #pragma unroll
                for (int k = 0; k < 4; k++) {
                    float lo = __uint_as_float((unsigned)(acc[k][j] & 0xffffffffull));
                    float hi = __uint_as_float((unsigned)(acc[k][j] >> 32));
                    float s = es - (lo + hi);
                    if (s < best[k]) { best[k] = s; bidx[k] = code; }
                }
            }
            __syncthreads();
        }

        #pragma unroll
        for (int k = 0; k < 4; k++) {
            float b1 = best[k]; int i1 = bidx[k];
            #pragma unroll
            for (int off = 4; off <= 16; off <<= 1) {
                float ob = __shfl_xor_sync(0xffffffffu, b1, off);
                int   oi = __shfl_xor_sync(0xffffffffu, i1, off);
                if (ob < b1 || (ob == b1 && oi < i1)) { b1 = ob; i1 = oi; }
            }
            best[k] = b1; bidx[k] = i1;
        }
        if (csub == 0) {
            #pragma unroll
            for (int k = 0; k < 4; k++) {
                int r = row_t + 4 * k;
                rbf[wid * 16 + r] = best[k];
                rif[wid * 16 + r] = bidx[k];
            }
        }
        __syncthreads();

        if (tid < cnt) {
            float b1 = 3.4e38f; int i1 = 0;
            #pragma unroll
            for (int w = 0; w < 8; w++) {
                float ob = rbf[w * 16 + tid]; int oi = rif[w * 16 + tid];
                if (ob < b1 || (ob == b1 && oi < i1)) { b1 = ob; i1 = oi; }
            }
            const int row  = g_fix_list[base + tid];
            const int oldi = (int)out[ND + 2 + row];
            if (i1 != oldi) {
                float lold = 0.f, lnew = 0.f;
                #pragma unroll
                for (int d = 0; d < DIMV; d++) {
                    float zz = z[(size_t)row * DIMV + d];
                    float eo = cb[(size_t)oldi * DIMV + d];
                    float en = cb[(size_t)i1 * DIMV + d];
                    lold += (zz - eo) * (zz - eo);
                    lnew += (zz - en) * (zz - en);
                }
                atomicAdd(&g_loss_corr, lnew - lold);
                out[ND + 2 + row] = (float)i1;
                #pragma unroll
                for (int j = 0; j < 16; j++)
                    reinterpret_cast<float4*>(out + (size_t)row * DIMV)[j] =
                        reinterpret_cast<const float4*>(cb + (size_t)i1 * DIMV)[j];
            }
        }
    }
}

// ---------------- K4: deterministic final losses ----------------
__global__ void vq_finalize(float* __restrict__ out, int out_size) {
    __shared__ float ws[8];
    int tid = threadIdx.x;
    float s = 0.f;
    #pragma unroll
    for (int i = 0; i < NBLK / 256; i++) s += g_block_sums[tid + 256 * i];
    #pragma unroll
    for (int off = 16; off >= 1; off >>= 1)
        s += __shfl_xor_sync(0xffffffffu, s, off);
    if ((tid & 31) == 0) ws[tid >> 5] = s;
    __syncthreads();
    if (tid == 0) {
        float b = 0.f;
        #pragma unroll
        for (int w = 0; w < 8; w++) b += ws[w];
        float m = (b + g_loss_corr) / (float)ND;
        if (out_size >= ND + 2) {
            out[ND]     = m;   // vq_loss
            out[ND + 1] = m;   // commitment_loss
        }
    }
}

extern "C" void kernel_launch(void* const* d_in, const int* in_sizes, int n_in,
                              void* d_out, int out_size) {
    const float* a = (const float*)d_in[0];
    const float* b = (const float*)d_in[1];
    const float* z;
    const float* cb;
    if (in_sizes[0] == NV * DIMV) { z = a; cb = b; }
    else                          { z = b; cb = a; }
    float* out = (float*)d_out;

    cudaFuncSetAttribute(vq_main,  cudaFuncAttributeMaxDynamicSharedMemorySize, SMEM_MAIN);
    cudaFuncSetAttribute(vq_fixup, cudaFuncAttributeMaxDynamicSharedMemorySize, SMEM_FIX);

    vq_scan<<<256, 256>>>(z, cb);
    vq_qcb<<<KC / 128, 128>>>(cb);
    vq_main<<<NBLK, 256, SMEM_MAIN>>>(z, cb, out, out_size);
    vq_fixup<<<512, 256, SMEM_FIX>>>(z, cb, out, out_size);
    vq_finalize<<<1, 256>>>(out, out_size);
}

// round 16
// speedup vs baseline: 3.9847x; 3.9847x over previous
#include <cuda_runtime.h>
#include <cuda_fp16.h>
#include <cstdint>

#define NV   32768
#define KC   8192
#define DIMV 64
#define ND   (NV * DIMV)

#define CCHUNK  128                 // codes per chunk
#define NCHUNKS (KC / CCHUNK)       // 64
#define MTILE   128                 // z rows per block
#define NBLK    (NV / MTILE)        // 256
#define ASTRIDE 144                 // bytes per fp16 row (128B + 16B pad)

// main smem layout (bytes)
#define SM_AH   0                   // 128 * 144 = 18432
#define SM_B    18432               // 2 bufs * 18432
#define SM_BB(i) (SM_B + (i) * 18432)
#define SM_ESQ  55296               // 2 * 512
#define SM_RB   56320               // 2*128 floats
#define SM_RB2  57344
#define SM_RI   58368
#define SM_WL   59392               // 8 floats
#define SMEM_MAIN 59424

// fixup geometry (proven R14/R15)
#define FROWS   16
#define FCCH    256
#define FNCH    (KC / FCCH)
#define FSTR    272
#define FEBUF   (FCCH * FSTR)
#define FSM_Z   0
#define FSM_E   4352
#define FSM_RED 143616
#define SMEM_FIX 144640

__device__ __align__(256) __half g_cbh[KC * DIMV];
__device__ float g_esq[KC];         // 0.5*||e||^2 exact fp32
__device__ float g_block_sums[NBLK];
__device__ unsigned g_maxne_bits;   // max_k ||e_k|| as float bits
__device__ int   g_fix_count;
__device__ int   g_fix_list[NV];
__device__ float g_loss_corr;

__device__ __forceinline__ void cp16(void* dst_s, const void* src_g) {
    uint32_t d = (uint32_t)__cvta_generic_to_shared(dst_s);
    asm volatile("cp.async.cg.shared.global [%0], [%1], 16;" :: "r"(d), "l"(src_g));
}
#define CP_COMMIT() asm volatile("cp.async.commit_group;" ::: "memory")
#define CP_WAIT1()  asm volatile("cp.async.wait_group 1;" ::: "memory")
#define CP_WAIT0()  asm volatile("cp.async.wait_group 0;" ::: "memory")

__device__ __forceinline__ void mma16816(float* c, const uint32_t* a,
                                         uint32_t b0, uint32_t b1) {
    asm volatile(
        "mma.sync.aligned.m16n8k16.row.col.f32.f16.f16.f32 "
        "{%0,%1,%2,%3}, {%4,%5,%6,%7}, {%8,%9}, {%0,%1,%2,%3};"
        : "+f"(c[0]), "+f"(c[1]), "+f"(c[2]), "+f"(c[3])
        : "r"(a[0]), "r"(a[1]), "r"(a[2]), "r"(a[3]), "r"(b0), "r"(b1));
}

__device__ __forceinline__ void ffma2(unsigned long long &d,
                                      unsigned long long a,
                                      unsigned long long b) {
    asm("fma.rn.f32x2 %0, %1, %2, %0;" : "+l"(d) : "l"(a), "l"(b));
}

// ---------------- K1: codebook fp16 + half-norms + maxnorm + resets ----------------
__global__ void vq_prep(const float* __restrict__ cb) {
    int k = blockIdx.x * blockDim.x + threadIdx.x;
    if (k == 0) { g_fix_count = 0; g_loss_corr = 0.f; }
    if (k < KC) {
        float s = 0.f;
        #pragma unroll
        for (int d = 0; d < DIMV; d++) {
            float v = cb[(size_t)k * DIMV + d];
            s += v * v;
            g_cbh[(size_t)k * DIMV + d] = __float2half_rn(v);
        }
        g_esq[k] = 0.5f * s;
        float nrm = sqrtf(s);
        #pragma unroll
        for (int off = 16; off >= 1; off >>= 1)
            nrm = fmaxf(nrm, __shfl_xor_sync(0xffffffffu, nrm, off));
        if ((threadIdx.x & 31) == 0)
            atomicMax(&g_maxne_bits, __float_as_uint(nrm));  // idempotent across replays
    }
}

// ---------------- K2: single fp16 HMMA GEMM + argmin/margin + gather ----------------
__device__ __forceinline__ void cp_chunk(char* smem, int chunk, int buf, int tid) {
    const __half* sh = g_cbh + (size_t)chunk * CCHUNK * DIMV;
    char* dh = smem + SM_BB(buf);
    #pragma unroll
    for (int n = 0; n < 4; n++) {
        int q = tid + 256 * n;          // 0..1023 16B-quads
        int code = q >> 3, dd = q & 7;
        cp16(dh + code * ASTRIDE + dd * 16, sh + code * DIMV + dd * 8);
    }
    if (tid < 32)
        cp16(smem + SM_ESQ + (buf ? 512 : 0) + tid * 16, g_esq + chunk * CCHUNK + tid * 4);
}

__global__ __launch_bounds__(256, 2) void vq_main(
    const float* __restrict__ z, const float* __restrict__ cb,
    float* __restrict__ out, int out_size)
{
    extern __shared__ char smem[];
    const int tid = threadIdx.x, lane = tid & 31, wid = tid >> 5;
    const int g = lane >> 2, t = lane & 3;
    const int mwarp = wid >> 1, nwarp = wid & 1;
    const int row0 = blockIdx.x * MTILE;

    // A tile: z fp32 -> fp16 (hi only)
    #pragma unroll
    for (int n = 0; n < 16; n++) {
        int i = tid + 256 * n;          // 0..4095 float2 slots
        int r = i >> 5, d2 = i & 31;
        float2 v = reinterpret_cast<const float2*>(z + (size_t)(row0 + r) * DIMV)[d2];
        *reinterpret_cast<__half2*>(smem + SM_AH + r * ASTRIDE + d2 * 4) =
            __halves2half2(__float2half_rn(v.x), __float2half_rn(v.y));
    }

    cp_chunk(smem, 0, 0, tid);
    CP_COMMIT();
    __syncthreads();

    float best[4], best2[4];
    int   bidx[4];
    #pragma unroll
    for (int s = 0; s < 4; s++) { best[s] = 3.4e38f; best2[s] = 3.4e38f; bidx[s] = 0; }

    const char* Ah = smem + SM_AH;
    const int abase = (mwarp * 32 + g) * ASTRIDE + t * 4;
    const int bbase = (nwarp * 64 + g) * ASTRIDE + t * 4;

    for (int c = 0; c < NCHUNKS; c++) {
        const int b = c & 1;
        if (c + 1 < NCHUNKS) { cp_chunk(smem, c + 1, (c + 1) & 1, tid); CP_COMMIT(); CP_WAIT1(); }
        else                 { CP_WAIT0(); }
        __syncthreads();

        const char* Bh = smem + SM_BB(b);
        const float* esq_s = reinterpret_cast<const float*>(smem + SM_ESQ + (b ? 512 : 0));

        float acc[2][8][4];
        #pragma unroll
        for (int mm = 0; mm < 2; mm++)
            #pragma unroll
            for (int nt = 0; nt < 8; nt++)
                #pragma unroll
                for (int q = 0; q < 4; q++) acc[mm][nt][q] = 0.f;

        #pragma unroll
        for (int ks = 0; ks < 4; ks++) {
            uint32_t ahf[2][4];
            #pragma unroll
            for (int mm = 0; mm < 2; mm++) {
                int ao = abase + mm * 16 * ASTRIDE + ks * 32;
                ahf[mm][0] = *reinterpret_cast<const uint32_t*>(Ah + ao);
                ahf[mm][1] = *reinterpret_cast<const uint32_t*>(Ah + ao + 8 * ASTRIDE);
                ahf[mm][2] = *reinterpret_cast<const uint32_t*>(Ah + ao + 16);
                ahf[mm][3] = *reinterpret_cast<const uint32_t*>(Ah + ao + 8 * ASTRIDE + 16);
            }
            #pragma unroll
            for (int nt = 0; nt < 8; nt++) {
                int bo = bbase + nt * 8 * ASTRIDE + ks * 32;
                uint32_t bh0 = *reinterpret_cast<const uint32_t*>(Bh + bo);
                uint32_t bh1 = *reinterpret_cast<const uint32_t*>(Bh + bo + 16);
                #pragma unroll
                for (int mm = 0; mm < 2; mm++)
                    mma16816(acc[mm][nt], ahf[mm], bh0, bh1);
            }
        }

        #pragma unroll
        for (int nt = 0; nt < 8; nt++) {
            int nloc = nwarp * 64 + nt * 8 + 2 * t;
            float es0 = esq_s[nloc], es1 = esq_s[nloc + 1];
            int n0 = c * CCHUNK + nloc;
            #pragma unroll
            for (int mm = 0; mm < 2; mm++) {
                int s0 = mm * 2, s1 = mm * 2 + 1;
                float v00 = es0 - acc[mm][nt][0];
                float v01 = es1 - acc[mm][nt][1];
                float v10 = es0 - acc[mm][nt][2];
                float v11 = es1 - acc[mm][nt][3];
                if (v00 < best[s0]) { best2[s0] = best[s0]; best[s0] = v00; bidx[s0] = n0; }
                else if (v00 < best2[s0]) best2[s0] = v00;
                if (v01 < best[s0]) { best2[s0] = best[s0]; best[s0] = v01; bidx[s0] = n0 + 1; }
                else if (v01 < best2[s0]) best2[s0] = v01;
                if (v10 < best[s1]) { best2[s1] = best[s1]; best[s1] = v10; bidx[s1] = n0; }
                else if (v10 < best2[s1]) best2[s1] = v10;
                if (v11 < best[s1]) { best2[s1] = best[s1]; best[s1] = v11; bidx[s1] = n0 + 1; }
                else if (v11 < best2[s1]) best2[s1] = v11;
            }
        }
        __syncthreads();
    }

    // reduce over t (lanes xor 1,2 share rows)
    #pragma unroll
    for (int s = 0; s < 4; s++) {
        float b1 = best[s], b2 = best2[s];
        int   i1 = bidx[s];
        #pragma unroll
        for (int off = 1; off <= 2; off <<= 1) {
            float ob  = __shfl_xor_sync(0xffffffffu, b1, off);
            float ob2 = __shfl_xor_sync(0xffffffffu, b2, off);
            int   oi  = __shfl_xor_sync(0xffffffffu, i1, off);
            if (ob < b1 || (ob == b1 && oi < i1)) { b2 = fminf(b1, ob2); b1 = ob; i1 = oi; }
            else                                  { b2 = fminf(ob, b2); }
        }
        best[s] = b1; best2[s] = b2; bidx[s] = i1;
    }
    if (t == 0) {
        float* rb  = reinterpret_cast<float*>(smem + SM_RB);
        float* rb2 = reinterpret_cast<float*>(smem + SM_RB2);
        int*   ri  = reinterpret_cast<int*>(smem + SM_RI);
        #pragma unroll
        for (int s = 0; s < 4; s++) {
            int row = mwarp * 32 + (s >> 1) * 16 + g + (s & 1) * 8;
            rb [nwarp * 128 + row] = best[s];
            rb2[nwarp * 128 + row] = best2[s];
            ri [nwarp * 128 + row] = bidx[s];
        }
    }
    __syncthreads();

    float lsum = 0.f;
    if (tid < MTILE) {
        const float* rb  = reinterpret_cast<const float*>(smem + SM_RB);
        const float* rb2 = reinterpret_cast<const float*>(smem + SM_RB2);
        const int*   ri  = reinterpret_cast<const int*>(smem + SM_RI);
        float b0 = rb[tid],       b20 = rb2[tid];       int i0 = ri[tid];
        float b1 = rb[128 + tid], b21 = rb2[128 + tid]; int i1 = ri[128 + tid];
        float bb, bb2; int bi;
        if (b1 < b0 || (b1 == b0 && i1 < i0)) { bb = b1; bi = i1; bb2 = fminf(b0, b21); }
        else                                  { bb = b0; bi = i0; bb2 = fminf(b1, b20); }

        const int grow = row0 + tid;
        const float4* crow = reinterpret_cast<const float4*>(cb + (size_t)bi * DIMV);
        const float4* zrow = reinterpret_cast<const float4*>(z + (size_t)grow * DIMV);
        float4* qrow = reinterpret_cast<float4*>(out + (size_t)grow * DIMV);
        float zsq = 0.f;
        #pragma unroll
        for (int j = 0; j < 16; j++) {
            float4 e = crow[j], zz = zrow[j];
            qrow[j] = e;                    // straight-through: quantized == codebook[idx]
            float dx = zz.x - e.x, dy = zz.y - e.y;
            float dz = zz.z - e.z, dw = zz.w - e.w;
            lsum += dx * dx + dy * dy + dz * dz + dw * dw;
            zsq  += zz.x * zz.x + zz.y * zz.y + zz.z * zz.z + zz.w * zz.w;
        }
        // rigorous fp16-rounding bound: B = 2^-10 * ||z|| * max||e|| * 1.01 + 1e-3
        float B = sqrtf(zsq) * __uint_as_float(g_maxne_bits) * (1.01f / 1024.f) + 1e-3f;
        if (bb2 - bb < 2.f * B) {
            int pos = atomicAdd(&g_fix_count, 1);
            g_fix_list[pos] = grow;
        }
        if (out_size >= ND + 2 + NV) out[ND + 2 + grow] = (float)bi;
    }

    #pragma unroll
    for (int off = 16; off >= 1; off >>= 1)
        lsum += __shfl_xor_sync(0xffffffffu, lsum, off);
    float* wl = reinterpret_cast<float*>(smem + SM_WL);
    if (lane == 0) wl[wid] = lsum;
    __syncthreads();
    if (tid == 0) {
        float bsum = 0.f;
        #pragma unroll
        for (int w = 0; w < 8; w++) bsum += wl[w];
        g_block_sums[blockIdx.x] = bsum;
    }
}

// ---------------- K3: exact fp32 rescan of flagged rows (proven R14/R15) ----------------
__global__ __launch_bounds__(256, 1) void vq_fixup(
    const float* __restrict__ z, const float* __restrict__ cb,
    float* __restrict__ out, int out_size)
{
    extern __shared__ char fsm[];
    if (out_size < ND + 2 + NV) return;
    const int tid = threadIdx.x, lane = tid & 31, wid = tid >> 5;
    const int row_t = lane & 3, csub = lane >> 2;
    const int ct = wid * 8 + csub;
    int nfix = g_fix_count; if (nfix > NV) nfix = NV;

    float* z_s = reinterpret_cast<float*>(fsm + FSM_Z);
    float* rbf = reinterpret_cast<float*>(fsm + FSM_RED);
    int*   rif = reinterpret_cast<int*>(rbf + 128);

    for (int g = blockIdx.x; g * FROWS < nfix; g += gridDim.x) {
        const int base = g * FROWS;
        const int cnt  = min(FROWS, nfix - base);
        __syncthreads();

        for (int i = tid; i < FROWS * 16; i += 256) {
            int r = i >> 4, qd = i & 15;
            int zr = g_fix_list[base + min(r, cnt - 1)];
            float4 v = reinterpret_cast<const float4*>(z + (size_t)zr * DIMV)[qd];
            *reinterpret_cast<float4*>(z_s + r * 68 + qd * 4) = v;
        }
        #pragma unroll
        for (int n = 0; n < 16; n++) {
            int q = tid + 256 * n;
            int code = q >> 4, dd = q & 15;
            cp16(fsm + FSM_E + code * FSTR + dd * 16, cb + (size_t)code * DIMV + dd * 4);
        }
        CP_COMMIT();

        float best[4];
        int   bidx[4];
        #pragma unroll
        for (int k = 0; k < 4; k++) { best[k] = 3.4e38f; bidx[k] = 0; }

        for (int c = 0; c < FNCH; c++) {
            const int b = c & 1;
            if (c + 1 < FNCH) {
                const float* src = cb + (size_t)(c + 1) * FCCH * DIMV;
                char* d = fsm + FSM_E + ((c + 1) & 1) * FEBUF;
                #pragma unroll
                for (int n = 0; n < 16; n++) {
                    int q = tid + 256 * n;
                    int code = q >> 4, dd = q & 15;
                    cp16(d + code * FSTR + dd * 16, src + (size_t)code * DIMV + dd * 4);
                }
                CP_COMMIT(); CP_WAIT1();
            } else CP_WAIT0();
            __syncthreads();

            const char* Eb = fsm + FSM_E + b * FEBUF;
            unsigned long long acc[4][4];
            #pragma unroll
            for (int k = 0; k < 4; k++)
                #pragma unroll
                for (int j = 0; j < 4; j++) acc[k][j] = 0ull;

            #pragma unroll 8
            for (int d2 = 0; d2 < 32; d2++) {
                unsigned long long zf[4], ef[4];
                #pragma unroll
                for (int k = 0; k < 4; k++)
                    zf[k] = *reinterpret_cast<const unsigned long long*>(
                        z_s + (row_t + 4 * k) * 68 + d2 * 2);
                #pragma unroll
                for (int j = 0; j < 4; j++)
                    ef[j] = *reinterpret_cast<const unsigned long long*>(
                        Eb + (ct + 64 * j) * FSTR + d2 * 8);
                #pragma unroll
                for (int k = 0; k < 4; k++)
                    #pragma unroll
                    for (int j = 0; j < 4; j++) ffma2(acc[k][j], zf[k], ef[j]);
            }

            #pragma unroll
            for (int j = 0; j < 4; j++) {
                int code = c * FCCH + ct + 64 * j;
                float es = __ldg(&g_esq[code]);
                #pragma unroll
                for (int k = 0; k < 4; k++) {
                    float lo = __uint_as_float((unsigned)(acc[k][j] & 0xffffffffull));
                    float hi = __uint_as_float((unsigned)(acc[k][j] >> 32));
                    float s = es - (lo + hi);
                    if (s < best[k]) { best[k] = s; bidx[k] = code; }
                }
            }
            __syncthreads();
        }

        #pragma unroll
        for (int k = 0; k < 4; k++) {
            float b1 = best[k]; int i1 = bidx[k];
            #pragma unroll
            for (int off = 4; off <= 16; off <<= 1) {
                float ob = __shfl_xor_sync(0xffffffffu, b1, off);
                int   oi = __shfl_xor_sync(0xffffffffu, i1, off);
                if (ob < b1 || (ob == b1 && oi < i1)) { b1 = ob; i1 = oi; }
            }
            best[k] = b1; bidx[k] = i1;
        }
        if (csub == 0) {
            #pragma unroll
            for (int k = 0; k < 4; k++) {
                int r = row_t + 4 * k;
                rbf[wid * 16 + r] = best[k];
                rif[wid * 16 + r] = bidx[k];
            }
        }
        __syncthreads();

        if (tid < cnt) {
            float b1 = 3.4e38f; int i1 = 0;
            #pragma unroll
            for (int w = 0; w < 8; w++) {
                float ob = rbf[w * 16 + tid]; int oi = rif[w * 16 + tid];
                if (ob < b1 || (ob == b1 && oi < i1)) { b1 = ob; i1 = oi; }
            }
            const int row  = g_fix_list[base + tid];
            const int oldi = (int)out[ND + 2 + row];
            if (i1 != oldi) {
                float lold = 0.f, lnew = 0.f;
                #pragma unroll
                for (int d = 0; d < DIMV; d++) {
                    float zz = z[(size_t)row * DIMV + d];
                    float eo = cb[(size_t)oldi * DIMV + d];
                    float en = cb[(size_t)i1 * DIMV + d];
                    lold += (zz - eo) * (zz - eo);
                    lnew += (zz - en) * (zz - en);
                }
                atomicAdd(&g_loss_corr, lnew - lold);
                out[ND + 2 + row] = (float)i1;
                #pragma unroll
                for (int j = 0; j < 16; j++)
                    reinterpret_cast<float4*>(out + (size_t)row * DIMV)[j] =
                        reinterpret_cast<const float4*>(cb + (size_t)i1 * DIMV)[j];
            }
        }
    }
}

// ---------------- K4: deterministic final losses ----------------
__global__ void vq_finalize(float* __restrict__ out, int out_size) {
    __shared__ float ws[8];
    int tid = threadIdx.x;
    float s = g_block_sums[tid];        // NBLK == 256
    #pragma unroll
    for (int off = 16; off >= 1; off >>= 1)
        s += __shfl_xor_sync(0xffffffffu, s, off);
    if ((tid & 31) == 0) ws[tid >> 5] = s;
    __syncthreads();
    if (tid == 0) {
        float b = 0.f;
        #pragma unroll
        for (int w = 0; w < 8; w++) b += ws[w];
        float m = (b + g_loss_corr) / (float)ND;
        if (out_size >= ND + 2) {
            out[ND]     = m;   // vq_loss
            out[ND + 1] = m;   // commitment_loss
        }
    }
}

extern "C" void kernel_launch(void* const* d_in, const int* in_sizes, int n_in,
                              void* d_out, int out_size) {
    const float* a = (const float*)d_in[0];
    const float* b = (const float*)d_in[1];
    const float* z;
    const float* cb;
    if (in_sizes[0] == NV * DIMV) { z = a; cb = b; }
    else                          { z = b; cb = a; }
    float* out = (float*)d_out;

    cudaFuncSetAttribute(vq_main,  cudaFuncAttributeMaxDynamicSharedMemorySize, SMEM_MAIN);
    cudaFuncSetAttribute(vq_fixup, cudaFuncAttributeMaxDynamicSharedMemorySize, SMEM_FIX);

    vq_prep<<<KC / 128, 128>>>(cb);
    vq_main<<<NBLK, 256, SMEM_MAIN>>>(z, cb, out, out_size);
    vq_fixup<<<512, 256, SMEM_FIX>>>(z, cb, out, out_size);
    vq_finalize<<<1, 256>>>(out, out_size);
}